// round 8
// baseline (speedup 1.0000x reference)
#include <cuda_runtime.h>
#include <cuda_fp16.h>

#define N_NODES     100000
#define IN_DIM      128
#define NUM_ET      16
#define E_PER_TYPE  100000
#define N_EDGES     (NUM_ET * E_PER_TYPE)   // 1,600,000

#define EDGES_PER_WARP   32
#define WARPS_PER_BLOCK  8
#define WARPS_PER_TYPE   (E_PER_TYPE / EDGES_PER_WARP)   // 3125
#define TOTAL_BLOCKS     (N_EDGES / (EDGES_PER_WARP * WARPS_PER_BLOCK))  // 6250

// fp16 copy of z (25.6 MB scratch — static __device__, no allocation)
__device__ __align__(16) __half g_zh[N_NODES * IN_DIM];

// ---------------- conversion: z fp32 -> fp16 ----------------
__global__ __launch_bounds__(256)
void convert_z_kernel(const float* __restrict__ z)
{
    const int i = blockIdx.x * blockDim.x + threadIdx.x;  // 8 floats per thread
    if (i >= N_NODES * IN_DIM / 8) return;
    const float4 v0 = ((const float4*)z)[2 * i];
    const float4 v1 = ((const float4*)z)[2 * i + 1];
    __half2 h0 = __floats2half2_rn(v0.x, v0.y);
    __half2 h1 = __floats2half2_rn(v0.z, v0.w);
    __half2 h2 = __floats2half2_rn(v1.x, v1.y);
    __half2 h3 = __floats2half2_rn(v1.z, v1.w);
    uint4 o;
    o.x = *(unsigned*)&h0; o.y = *(unsigned*)&h1;
    o.z = *(unsigned*)&h2; o.w = *(unsigned*)&h3;
    ((uint4*)g_zh)[i] = o;
}

// ---------------- main: warp-per-edge loads (1 line per LDG), 32 edges/warp ----------------
// lane k covers dims {2k,2k+1} (line 0) and {64+2k,65+2k} (line 1) of each row.
// Every z-LDG is 32 lanes x 4B = exactly one 128B line -> 1.0 cyc/wavefront (no replays).
__global__ __launch_bounds__(256)
void mipd_f16_kernel(const float* __restrict__ w,
                     const int*   __restrict__ ei,
                     float* __restrict__ out)
{
    const int warp_in_blk = threadIdx.x >> 5;
    const int lane        = threadIdx.x & 31;
    const int warp_gid    = blockIdx.x * WARPS_PER_BLOCK + warp_in_blk;
    const int edge_base   = warp_gid * EDGES_PER_WARP;          // global edge id of edge 0
    const int t           = warp_gid / WARPS_PER_TYPE;          // edge type (warp is single-type)
    const int i0          = edge_base - t * E_PER_TYPE;         // within-type base

    __shared__ float red[WARPS_PER_BLOCK][EDGES_PER_WARP][4];   // 4 KB
    float (*myred)[4] = red[warp_in_blk];

    // weights for this lane's 4 dims (fp32, held in regs for all 32 edges)
    const float2 wf0 = *(const float2*)(w + t * IN_DIM + 2 * lane);
    const float2 wf1 = *(const float2*)(w + t * IN_DIM + 64 + 2 * lane);

    // preload this warp's 32 src + 32 dst indices (2 coalesced LDGs)
    const int* ei_t   = ei + t * (2 * E_PER_TYPE);
    const int  src_my = ei_t[i0 + lane];
    const int  dst_my = ei_t[E_PER_TYPE + i0 + lane];

    const __half2* zh2 = (const __half2*)g_zh;   // row = 64 half2

    #pragma unroll 4
    for (int e = 0; e < EDGES_PER_WARP; ++e) {
        const int s_e = __shfl_sync(0xffffffffu, src_my, e);
        const int d_e = __shfl_sync(0xffffffffu, dst_my, e);
        const __half2* za = zh2 + (size_t)s_e * 64;
        const __half2* zb = zh2 + (size_t)d_e * 64;
        const __half2 a0 = za[lane];        // line 0 of src row (one 128B line)
        const __half2 a1 = za[32 + lane];   // line 1
        const __half2 b0 = zb[lane];
        const __half2 b1 = zb[32 + lane];

        // same arithmetic profile as R7: fp16 products, fp32 weighted accumulate
        const float2 p = __half22float2(__hmul2(a0, b0));
        const float2 q = __half22float2(__hmul2(a1, b1));
        float s = p.x * wf0.x;
        s = fmaf(p.y, wf0.y, s);
        s = fmaf(q.x, wf1.x, s);
        s = fmaf(q.y, wf1.y, s);

        // 3-stage butterfly: lanes 0,8,16,24 hold the 4 octet partials
        s += __shfl_xor_sync(0xffffffffu, s, 1);
        s += __shfl_xor_sync(0xffffffffu, s, 2);
        s += __shfl_xor_sync(0xffffffffu, s, 4);
        if ((lane & 7) == 0) myred[e][lane >> 3] = s;
    }
    __syncwarp();

    // phase 2: lane e finishes edge e (4 adds + sigmoid), fully coalesced stores
    const float4 p4 = *(const float4*)myred[lane];
    const float sv  = (p4.x + p4.y) + (p4.z + p4.w);
    const float v   = 1.0f / (1.0f + __expf(-sv));
    out[edge_base + lane]           = v;   // per_type (16,100000) row-major
    out[N_EDGES + edge_base + lane] = v;   // score (same values flattened)
}

extern "C" void kernel_launch(void* const* d_in, const int* in_sizes, int n_in,
                              void* d_out, int out_size)
{
    const float* z  = (const float*)d_in[0];   // (100000, 128) fp32
    const float* w  = (const float*)d_in[1];   // (16, 128) fp32
    const int*   ei = (const int*)d_in[2];     // (16, 2, 100000) int32
    float*       out = (float*)d_out;          // 3,200,000 fp32

    // 1) stage z as fp16
    const int conv_threads = N_NODES * IN_DIM / 8;     // 1.6M
    convert_z_kernel<<<(conv_threads + 255) / 256, 256>>>(z);

    // 2) decode
    mipd_f16_kernel<<<TOTAL_BLOCKS, 256>>>(w, ei, out);
}

// round 10
// speedup vs baseline: 1.3467x; 1.3467x over previous
#include <cuda_runtime.h>
#include <cuda_fp16.h>

#define N_NODES     100000
#define IN_DIM      128
#define NUM_ET      16
#define E_PER_TYPE  100000
#define N_EDGES     (NUM_ET * E_PER_TYPE)   // 1,600,000

#define EDGES_PER_WARP   32
#define WARPS_PER_TYPE   (E_PER_TYPE / EDGES_PER_WARP)               // 3125 (exact)
#define TOTAL_BLOCKS     (N_EDGES / (EDGES_PER_WARP * 8))            // 6250

// fp16 copy of z (25.6 MB scratch — static __device__, no allocation)
__device__ __align__(16) __half g_zh[N_NODES * IN_DIM];

// ---------------- conversion: z fp32 -> fp16 ----------------
__global__ __launch_bounds__(256)
void convert_z_kernel(const float* __restrict__ z)
{
    const int i = blockIdx.x * blockDim.x + threadIdx.x;  // 8 floats per thread
    if (i >= N_NODES * IN_DIM / 8) return;
    const float4 v0 = ((const float4*)z)[2 * i];
    const float4 v1 = ((const float4*)z)[2 * i + 1];
    __half2 h0 = __floats2half2_rn(v0.x, v0.y);
    __half2 h1 = __floats2half2_rn(v0.z, v0.w);
    __half2 h2 = __floats2half2_rn(v1.x, v1.y);
    __half2 h3 = __floats2half2_rn(v1.z, v1.w);
    uint4 o;
    o.x = *(unsigned*)&h0; o.y = *(unsigned*)&h1;
    o.z = *(unsigned*)&h2; o.w = *(unsigned*)&h3;
    ((uint4*)g_zh)[i] = o;
}

// ---------------- main: 8 lanes/edge, 4 edges/warp-iter, 32 edges/warp ----------------
// Lane l (=lane&7) covers halves [8l,8l+8) (line 0) and [64+8l,64+8l+8) (line 1).
// All products and the weighted accumulate run in half2 (HMUL2/HFMA2); one
// half2->float2 conversion per edge, then a 3-stage octet shuffle reduce.
__global__ __launch_bounds__(256)
void mipd_f16_kernel(const float* __restrict__ w,
                     const int*   __restrict__ ei,
                     float* __restrict__ out)
{
    const int warp_in_blk = threadIdx.x >> 5;
    const int lane        = threadIdx.x & 31;
    const int q           = lane >> 3;           // edge slot within 4-edge group
    const int l           = lane & 7;            // lane within edge

    const int warp_gid  = blockIdx.x * 8 + warp_in_blk;
    const int edge_base = warp_gid * EDGES_PER_WARP;      // global edge id of edge 0
    const int t         = warp_gid / WARPS_PER_TYPE;      // warp never spans types
    const int i0        = edge_base - t * E_PER_TYPE;     // within-type base

    // weights for this lane's 16 dims, converted once to half2 (amortized over 32 edges)
    const float* wrow = w + t * IN_DIM;
    const float4 wA = *(const float4*)(wrow + 8 * l);
    const float4 wB = *(const float4*)(wrow + 8 * l + 4);
    const float4 wC = *(const float4*)(wrow + 64 + 8 * l);
    const float4 wD = *(const float4*)(wrow + 64 + 8 * l + 4);
    __half2 wh[8];
    wh[0] = __floats2half2_rn(wA.x, wA.y); wh[1] = __floats2half2_rn(wA.z, wA.w);
    wh[2] = __floats2half2_rn(wB.x, wB.y); wh[3] = __floats2half2_rn(wB.z, wB.w);
    wh[4] = __floats2half2_rn(wC.x, wC.y); wh[5] = __floats2half2_rn(wC.z, wC.w);
    wh[6] = __floats2half2_rn(wD.x, wD.y); wh[7] = __floats2half2_rn(wD.z, wD.w);

    // preload this warp's 32 src + 32 dst indices (2 coalesced LDGs)
    const int* ei_t   = ei + t * (2 * E_PER_TYPE);
    const int  src_my = ei_t[i0 + lane];
    const int  dst_my = ei_t[E_PER_TYPE + i0 + lane];

    const __half* zh = g_zh;

    #pragma unroll
    for (int e4 = 0; e4 < EDGES_PER_WARP / 4; ++e4) {
        const int eslot = 4 * e4 + q;                       // this octet's edge (0..31)
        const int s_e = __shfl_sync(0xffffffffu, src_my, eslot);
        const int d_e = __shfl_sync(0xffffffffu, dst_my, eslot);

        const __half* arow = zh + (size_t)s_e * IN_DIM;
        const __half* brow = zh + (size_t)d_e * IN_DIM;
        const uint4 a0 = *(const uint4*)(arow + 8 * l);         // line 0 halves
        const uint4 a1 = *(const uint4*)(arow + 64 + 8 * l);    // line 1 halves
        const uint4 b0 = *(const uint4*)(brow + 8 * l);
        const uint4 b1 = *(const uint4*)(brow + 64 + 8 * l);

        const __half2* ha0 = (const __half2*)&a0;
        const __half2* ha1 = (const __half2*)&a1;
        const __half2* hb0 = (const __half2*)&b0;
        const __half2* hb1 = (const __half2*)&b1;

        // weighted accumulate fully in half2
        __half2 s2 = __hmul2(__hmul2(ha0[0], hb0[0]), wh[0]);
        s2 = __hfma2(__hmul2(ha0[1], hb0[1]), wh[1], s2);
        s2 = __hfma2(__hmul2(ha0[2], hb0[2]), wh[2], s2);
        s2 = __hfma2(__hmul2(ha0[3], hb0[3]), wh[3], s2);
        s2 = __hfma2(__hmul2(ha1[0], hb1[0]), wh[4], s2);
        s2 = __hfma2(__hmul2(ha1[1], hb1[1]), wh[5], s2);
        s2 = __hfma2(__hmul2(ha1[2], hb1[2]), wh[6], s2);
        s2 = __hfma2(__hmul2(ha1[3], hb1[3]), wh[7], s2);

        const float2 f = __half22float2(s2);
        float s = f.x + f.y;

        // reduce across the 8 lanes of this edge
        s += __shfl_xor_sync(0xffffffffu, s, 4);
        s += __shfl_xor_sync(0xffffffffu, s, 2);
        s += __shfl_xor_sync(0xffffffffu, s, 1);

        if (l == 0) {
            const float v = 1.0f / (1.0f + __expf(-s));
            const int g = edge_base + eslot;     // lanes 0,8,16,24 -> 4 consecutive floats
            out[g]           = v;                // per_type (16,100000) row-major
            out[N_EDGES + g] = v;                // score (same values flattened)
        }
    }
}

extern "C" void kernel_launch(void* const* d_in, const int* in_sizes, int n_in,
                              void* d_out, int out_size)
{
    const float* z  = (const float*)d_in[0];   // (100000, 128) fp32
    const float* w  = (const float*)d_in[1];   // (16, 128) fp32
    const int*   ei = (const int*)d_in[2];     // (16, 2, 100000) int32
    float*       out = (float*)d_out;          // 3,200,000 fp32

    // 1) stage z as fp16
    const int conv_threads = N_NODES * IN_DIM / 8;     // 1.6M
    convert_z_kernel<<<(conv_threads + 255) / 256, 256>>>(z);

    // 2) decode
    mipd_f16_kernel<<<TOTAL_BLOCKS, 256>>>(w, ei, out);
}